// round 15
// baseline (speedup 1.0000x reference)
#include <cuda_runtime.h>
#include <cuda_bf16.h>
#include <cstdint>

#define NB 4
#define NT 4096
#define NC 1024
#define NH 64
#define NROWS (NB * NT)

// bf16 hi/lo split q, k (row-major [row][h]); v transposed ([b][h][t]).
__device__ __nv_bfloat16 g_qhi[NROWS * NH];
__device__ __nv_bfloat16 g_qlo[NROWS * NH];
__device__ __nv_bfloat16 g_khi[NROWS * NH];
__device__ __nv_bfloat16 g_klo[NROWS * NH];
__device__ __nv_bfloat16 g_vthi[NB * NH * NT];
__device__ __nv_bfloat16 g_vtlo[NB * NH * NT];
// W transposed bf16 hi/lo: [192 cols][1024 c]  (q:0-63, k:64-127, v:128-191)
__device__ __nv_bfloat16 g_wthi[192 * NC];
__device__ __nv_bfloat16 g_wtlo[192 * NC];
// split-K partial accumulators
__device__ float g_oacc[NROWS * NH];
__device__ float g_lacc[NROWS];

// ===========================================================================
// Helpers (sm_80-era PTX: ldmatrix / mma.sync / cp.async — OK in compute_100)
// ===========================================================================
__device__ __forceinline__ uint32_t smem_u32(const void* p) {
    uint32_t a;
    asm("{ .reg .u64 t; cvta.to.shared.u64 t, %1; cvt.u32.u64 %0, t; }"
        : "=r"(a) : "l"(p));
    return a;
}
__device__ __forceinline__ void ldsm_x4(uint32_t* r, uint32_t addr) {
    asm volatile("ldmatrix.sync.aligned.m8n8.x4.shared.b16 {%0,%1,%2,%3}, [%4];"
                 : "=r"(r[0]), "=r"(r[1]), "=r"(r[2]), "=r"(r[3]) : "r"(addr));
}
__device__ __forceinline__ void mma_bf16(float* c, const uint32_t* a,
                                         uint32_t b0, uint32_t b1) {
    asm volatile(
        "mma.sync.aligned.m16n8k16.row.col.f32.bf16.bf16.f32 "
        "{%0,%1,%2,%3}, {%4,%5,%6,%7}, {%8,%9}, {%0,%1,%2,%3};"
        : "+f"(c[0]), "+f"(c[1]), "+f"(c[2]), "+f"(c[3])
        : "r"(a[0]), "r"(a[1]), "r"(a[2]), "r"(a[3]), "r"(b0), "r"(b1));
}
__device__ __forceinline__ uint32_t pack_bf16x2(float lo, float hi) {
    uint32_t r;
    asm("cvt.rn.bf16x2.f32 %0, %1, %2;" : "=r"(r) : "f"(hi), "f"(lo));
    return r;
}
#define CP16(dst, src) \
    asm volatile("cp.async.cg.shared.global [%0], [%1], 16;" :: "r"(dst), "l"(src))
#define CP_COMMIT() asm volatile("cp.async.commit_group;" ::: "memory")
#define CP_WAIT0()  asm volatile("cp.async.wait_group 0;" ::: "memory")
#define CP_WAIT1()  asm volatile("cp.async.wait_group 1;" ::: "memory")

// ===========================================================================
// Kernel 0: init — zero split-K accumulators; build transposed bf16 hi/lo W.
// ===========================================================================
__global__ void init_kernel(const float* __restrict__ Wq,
                            const float* __restrict__ Wk,
                            const float* __restrict__ Wv)
{
    const int tid = blockIdx.x * 256 + threadIdx.x;   // 0..131071
    float4 z = make_float4(0.f, 0.f, 0.f, 0.f);
#pragma unroll
    for (int i = tid; i < (NROWS * NH) / 4; i += 131072)
        reinterpret_cast<float4*>(g_oacc)[i] = z;
    if (tid < NROWS) g_lacc[tid] = 0.f;

    if (tid < 65536) {
        const int c = tid >> 6;      // 0..1023
        const int h = tid & 63;
        float wq = Wq[c * NH + h], wk = Wk[c * NH + h], wv = Wv[c * NH + h];
        __nv_bfloat16 h0 = __float2bfloat16(wq);
        __nv_bfloat16 h1 = __float2bfloat16(wk);
        __nv_bfloat16 h2 = __float2bfloat16(wv);
        g_wthi[(h)       * NC + c] = h0;
        g_wthi[(64 + h)  * NC + c] = h1;
        g_wthi[(128 + h) * NC + c] = h2;
        g_wtlo[(h)       * NC + c] = __float2bfloat16(wq - __bfloat162float(h0));
        g_wtlo[(64 + h)  * NC + c] = __float2bfloat16(wk - __bfloat162float(h1));
        g_wtlo[(128 + h) * NC + c] = __float2bfloat16(wv - __bfloat162float(h2));
    }
}

// ===========================================================================
// Kernel 1: QKV projection via mma.sync bf16 3-term split (exact R13 winner:
// 4 m-groups x 2 n-groups; B-fragment reuse across 2 m-tiles).
// ===========================================================================
#define QS_XSTG 36864                  // per X stage: hi 18432 + lo 18432
#define QS_W    73728
#define QS_WSTG 55296                  // hi 27648 + lo 27648
#define QS_TOTAL (QS_W + 2 * QS_WSTG)  // 184320 B

__global__ __launch_bounds__(256, 1)
void qkv_mma(const float* __restrict__ x)
{
    extern __shared__ char smem[];
    const uint32_t sb = smem_u32(smem);
    const int t    = threadIdx.x;
    const int w    = t >> 5;
    const int lane = t & 31;
    const int wm   = w & 3;            // m-group: rows [32*wm, 32*wm+32)
    const int wn   = w >> 2;           // n-group: cols [96*wn, 96*wn+96)
    const int row0 = blockIdx.x * 128;

    float acc[2][12][4];
#pragma unroll
    for (int mt = 0; mt < 2; ++mt)
#pragma unroll
        for (int j = 0; j < 12; ++j)
#pragma unroll
            for (int c = 0; c < 4; ++c) acc[mt][j][c] = 0.f;

    const uint32_t apat = (32 * wm + (lane & 15)) * 144 + (lane >> 4) * 16;
    const uint32_t bpat = ((96 * wn + ((lane >> 4) << 3) + (lane & 7)) * 144) +
                          ((lane >> 3) & 1) * 16;

    float4 xreg[8];
    auto load_x = [&](int c0) {
#pragma unroll
        for (int it = 0; it < 8; ++it) {
            int i   = t + it * 256;
            int row = i >> 4;
            int c4  = (i & 15) * 4;
            xreg[it] = *reinterpret_cast<const float4*>(
                x + (size_t)(row0 + row) * NC + c0 + c4);
        }
    };
    auto store_x = [&](int stage) {
        char* xb = smem + stage * QS_XSTG;
#pragma unroll
        for (int it = 0; it < 8; ++it) {
            int i   = t + it * 256;
            int row = i >> 4;
            int c4  = (i & 15) * 4;
            float4 v = xreg[it];
            float hx = __bfloat162float(__float2bfloat16(v.x));
            float hy = __bfloat162float(__float2bfloat16(v.y));
            float hz = __bfloat162float(__float2bfloat16(v.z));
            float hw = __bfloat162float(__float2bfloat16(v.w));
            uint2 hi2 = make_uint2(pack_bf16x2(v.x, v.y), pack_bf16x2(v.z, v.w));
            uint2 lo2 = make_uint2(pack_bf16x2(v.x - hx, v.y - hy),
                                   pack_bf16x2(v.z - hz, v.w - hw));
            uint32_t doff = row * 144 + c4 * 2;
            *reinterpret_cast<uint2*>(xb + doff)         = hi2;
            *reinterpret_cast<uint2*>(xb + 18432 + doff) = lo2;
        }
    };
    auto issue_w = [&](int stage, int c0) {
        uint32_t st = sb + QS_W + stage * QS_WSTG;
#pragma unroll
        for (int it = 0; it < 6; ++it) {
            int i   = t + it * 256;
            int col = i >> 3;
            int c8  = (i & 7) * 8;
            uint32_t doff = col * 144 + c8 * 2;
            CP16(st + doff,         g_wthi + (size_t)col * NC + c0 + c8);
            CP16(st + 27648 + doff, g_wtlo + (size_t)col * NC + c0 + c8);
        }
    };

    issue_w(0, 0);
    CP_COMMIT();
    load_x(0);
    store_x(0);
    load_x(64);

    for (int c = 0; c < 16; ++c) {
        __syncthreads();
        if (c < 15) { issue_w((c + 1) & 1, (c + 1) * 64); CP_COMMIT(); }
        if (c < 15) { CP_WAIT1(); } else { CP_WAIT0(); }
        __syncthreads();

        const uint32_t xst = sb + (c & 1) * QS_XSTG;
        const uint32_t wst = sb + QS_W + (c & 1) * QS_WSTG;
        uint32_t ah[2][4][4], al[2][4][4];
#pragma unroll
        for (int mt = 0; mt < 2; ++mt)
#pragma unroll
            for (int ks = 0; ks < 4; ++ks) {
                uint32_t a = xst + apat + mt * (16 * 144) + ks * 32;
                ldsm_x4(ah[mt][ks], a);
                ldsm_x4(al[mt][ks], a + 18432);
            }
#pragma unroll
        for (int n2 = 0; n2 < 6; ++n2) {
#pragma unroll
            for (int ks = 0; ks < 4; ++ks) {
                uint32_t bh[4], bl[4];
                uint32_t a = wst + bpat + n2 * (16 * 144) + ks * 32;
                ldsm_x4(bh, a);
                ldsm_x4(bl, a + 27648);
#pragma unroll
                for (int mt = 0; mt < 2; ++mt) {
                    float* cA = acc[mt][2 * n2];
                    float* cB = acc[mt][2 * n2 + 1];
                    mma_bf16(cA, ah[mt][ks], bh[0], bh[1]);
                    mma_bf16(cA, ah[mt][ks], bl[0], bl[1]);
                    mma_bf16(cA, al[mt][ks], bh[0], bh[1]);
                    mma_bf16(cB, ah[mt][ks], bh[2], bh[3]);
                    mma_bf16(cB, ah[mt][ks], bl[2], bl[3]);
                    mma_bf16(cB, al[mt][ks], bh[2], bh[3]);
                }
            }
        }
        if (c < 15) {
            store_x((c + 1) & 1);
            if (c < 14) load_x((c + 2) * 64);
        }
    }

    // ---- epilogue: split each result to bf16 hi/lo and scatter ----
#pragma unroll
    for (int mt = 0; mt < 2; ++mt) {
        const int ra = row0 + 32 * wm + 16 * mt + (lane >> 2);
#pragma unroll
        for (int j = 0; j < 12; ++j) {
            int col = 96 * wn + 8 * j + 2 * (lane & 3);
#pragma unroll
            for (int half = 0; half < 2; ++half) {
                int row = ra + 8 * half;
                float v0 = acc[mt][j][2 * half], v1 = acc[mt][j][2 * half + 1];
                float h0 = __bfloat162float(__float2bfloat16(v0));
                float h1 = __bfloat162float(__float2bfloat16(v1));
                uint32_t hi = pack_bf16x2(v0, v1);
                uint32_t lo = pack_bf16x2(v0 - h0, v1 - h1);
                if (col < 64) {
                    *reinterpret_cast<uint32_t*>(g_qhi + (size_t)row * NH + col) = hi;
                    *reinterpret_cast<uint32_t*>(g_qlo + (size_t)row * NH + col) = lo;
                } else if (col < 128) {
                    *reinterpret_cast<uint32_t*>(g_khi + (size_t)row * NH + col - 64) = hi;
                    *reinterpret_cast<uint32_t*>(g_klo + (size_t)row * NH + col - 64) = lo;
                } else {
                    int h  = col - 128;
                    int bb = row >> 12, tt = row & (NT - 1);
                    size_t i0 = ((size_t)bb * NH + h) * NT + tt;
                    g_vthi[i0]      = __float2bfloat16(v0);
                    g_vtlo[i0]      = __float2bfloat16(v0 - h0);
                    g_vthi[i0 + NT] = __float2bfloat16(v1);
                    g_vtlo[i0 + NT] = __float2bfloat16(v1 - h1);
                }
            }
        }
    }
}

// ===========================================================================
// Kernel 2: balanced split-K causal attention, 2 CTAs/SM, split-wait K/V.
// FULL 3-term PV restored (R14's P-lo drop gave rel_err 1.66e-3 — reverted).
// Kept from R14: 3 syncs/tile — issue_k after the V-wait barrier (which
// already proves S done everywhere); V-wait is CP_WAIT0.
// ===========================================================================
#define STG_KHI 0
#define STG_KLO 18432
#define STG_VHI 36864
#define STG_VLO 54272
#define STG_SZ  71680
#define SM_Q_HI STG_SZ                  // 71680
#define SM_Q_LO (SM_Q_HI + 9216)
#define SM_ATT_TOTAL (SM_Q_LO + 9216)   // 90112 B

__global__ __launch_bounds__(128, 2)
void attn_mma()
{
    extern __shared__ char smem[];
    const uint32_t sb = smem_u32(smem);
    const int t    = threadIdx.x;
    const int w    = t >> 5;          // 0..3
    const int lane = t & 31;

    const int bid = blockIdx.x;
    int g0  = bid * 14 + (bid < 80 ? bid : 80);
    int cnt = 14 + (bid < 80 ? 1 : 0);

    int b = g0 / 1056;
    int r = g0 % 1056;
    int qi = 0, cum = 0;
    while (cum + (qi >> 1) + 1 <= r) { cum += (qi >> 1) + 1; ++qi; }
    int kb = r - cum;

    const uint32_t kpat = ((((lane >> 4) << 3) + (lane & 7)) * 144) +
                          ((lane >> 3) & 1) * 16;
    const uint32_t vpat = ((((lane >> 4) << 3) + (lane & 7)) * 272) +
                          ((lane >> 3) & 1) * 16;
    const uint32_t qpat = (w * 16 + (lane & 15)) * 144 + (lane >> 4) * 16;

    auto issue_k = [&](int bb, int kbb) {
        int k0 = kbb * 128;
        const __nv_bfloat16* kh = g_khi + ((size_t)bb * NT + k0) * NH;
        const __nv_bfloat16* kl = g_klo + ((size_t)bb * NT + k0) * NH;
#pragma unroll
        for (int it = 0; it < 8; ++it) {
            int i   = t + it * 128;
            int row = i >> 3;
            int c8  = (i & 7) * 8;
            uint32_t doff = row * 144 + c8 * 2;
            CP16(sb + STG_KHI + doff, kh + row * NH + c8);
            CP16(sb + STG_KLO + doff, kl + row * NH + c8);
        }
    };
    auto issue_v = [&](int bb, int kbb) {
        int k0 = kbb * 128;
        const __nv_bfloat16* vh = g_vthi + (size_t)bb * NH * NT + k0;
        const __nv_bfloat16* vl = g_vtlo + (size_t)bb * NH * NT + k0;
#pragma unroll
        for (int it = 0; it < 8; ++it) {
            int i  = t + it * 128;
            int h  = i >> 4;
            int k8 = (i & 15) * 8;
            uint32_t doff = h * 272 + k8 * 2;
            CP16(sb + STG_VHI + doff, vh + (size_t)h * NT + k8);
            CP16(sb + STG_VLO + doff, vl + (size_t)h * NT + k8);
        }
    };
    auto load_q = [&](int bb, int qii) {
        const __nv_bfloat16* qh = g_qhi + ((size_t)bb * NT + qii * 64) * NH;
        const __nv_bfloat16* ql = g_qlo + ((size_t)bb * NT + qii * 64) * NH;
#pragma unroll
        for (int it = 0; it < 4; ++it) {
            int i   = t + it * 128;
            int row = i >> 3;
            int c8  = (i & 7) * 8;
            uint32_t doff = row * 144 + c8 * 2;
            *reinterpret_cast<uint4*>(smem + SM_Q_HI + doff) =
                *reinterpret_cast<const uint4*>(qh + row * NH + c8);
            *reinterpret_cast<uint4*>(smem + SM_Q_LO + doff) =
                *reinterpret_cast<const uint4*>(ql + row * NH + c8);
        }
    };

    uint32_t qh[4][4], ql[4][4];
    auto build_q = [&]() {
#pragma unroll
        for (int ks = 0; ks < 4; ++ks) {
            ldsm_x4(qh[ks], sb + SM_Q_HI + qpat + ks * 32);
            ldsm_x4(ql[ks], sb + SM_Q_LO + qpat + ks * 32);
        }
    };

    float o[8][4], l0, l1;
    auto zero_acc = [&]() {
#pragma unroll
        for (int j = 0; j < 8; ++j)
#pragma unroll
            for (int c = 0; c < 4; ++c) o[j][c] = 0.f;
        l0 = l1 = 0.f;
    };
    auto flush = [&](int bb, int qii) {
        float r0 = l0, r1 = l1;
        r0 += __shfl_xor_sync(0xffffffffu, r0, 1);
        r0 += __shfl_xor_sync(0xffffffffu, r0, 2);
        r1 += __shfl_xor_sync(0xffffffffu, r1, 1);
        r1 += __shfl_xor_sync(0xffffffffu, r1, 2);
        int rra = bb * NT + qii * 64 + w * 16 + (lane >> 2);
        if ((lane & 3) == 0) {
            atomicAdd(&g_lacc[rra], r0);
            atomicAdd(&g_lacc[rra + 8], r1);
        }
        float* o0 = g_oacc + (size_t)rra * NH;
        float* o1 = g_oacc + (size_t)(rra + 8) * NH;
#pragma unroll
        for (int j = 0; j < 8; ++j) {
            int h = 8 * j + 2 * (lane & 3);
            atomicAdd(o0 + h,     o[j][0]);
            atomicAdd(o0 + h + 1, o[j][1]);
            atomicAdd(o1 + h,     o[j][2]);
            atomicAdd(o1 + h + 1, o[j][3]);
        }
    };

    // ---- prologue: K and V as SEPARATE groups ----
    issue_k(b, kb);
    CP_COMMIT();
    issue_v(b, kb);
    CP_COMMIT();
    load_q(b, qi);
    __syncthreads();
    build_q();
    zero_acc();

    for (int it = 0; it < cnt; ++it) {
        int nb = b, nqi = qi, nkb = kb + 1;
        bool changed = false;
        if (nkb > (qi >> 1)) {
            nkb = 0; ++nqi; changed = true;
            if (nqi == 64) { nqi = 0; ++nb; }
        }
        const bool last = (it == cnt - 1);

        CP_WAIT1();                        // K_it done (pending {K_it, V_it})
        __syncthreads();                   // K visible to all warps

        const int k0 = kb * 128;
        const int ra = qi * 64 + w * 16 + (lane >> 2);
        const bool diag = (kb == (qi >> 1));

        // ---- S = Q K^T (reads K smem; full 3-term split) ----
        float s[16][4];
#pragma unroll
        for (int j = 0; j < 16; ++j)
#pragma unroll
            for (int c = 0; c < 4; ++c) s[j][c] = 0.f;
#pragma unroll
        for (int j2 = 0; j2 < 8; ++j2) {
            float* sA = s[2 * j2];
            float* sB = s[2 * j2 + 1];
#pragma unroll
            for (int ks = 0; ks < 4; ++ks) {
                uint32_t kh[4], kl[4];
                uint32_t a = sb + kpat + j2 * (16 * 144) + ks * 32;
                ldsm_x4(kh, a + STG_KHI);
                ldsm_x4(kl, a + STG_KLO);
                mma_bf16(sA, qh[ks], kh[0], kh[1]);
                mma_bf16(sA, qh[ks], kl[0], kl[1]);
                mma_bf16(sA, ql[ks], kh[0], kh[1]);
                mma_bf16(sB, qh[ks], kh[2], kh[3]);
                mma_bf16(sB, qh[ks], kl[2], kl[3]);
                mma_bf16(sB, ql[ks], kh[2], kh[3]);
            }
        }

        // ---- exp (+ causal mask on diagonal tile) — registers only ----
        if (diag) {
#pragma unroll
            for (int j = 0; j < 16; ++j) {
                int col = k0 + 8 * j + 2 * (lane & 3);
                float e0 = (col     <= ra)     ? __expf(s[j][0]) : 0.f;
                float e1 = (col + 1 <= ra)     ? __expf(s[j][1]) : 0.f;
                float e2 = (col     <= ra + 8) ? __expf(s[j][2]) : 0.f;
                float e3 = (col + 1 <= ra + 8) ? __expf(s[j][3]) : 0.f;
                s[j][0] = e0; s[j][1] = e1; s[j][2] = e2; s[j][3] = e3;
                l0 += e0 + e1; l1 += e2 + e3;
            }
        } else {
#pragma unroll
            for (int j = 0; j < 16; ++j) {
                float e0 = __expf(s[j][0]);
                float e1 = __expf(s[j][1]);
                float e2 = __expf(s[j][2]);
                float e3 = __expf(s[j][3]);
                s[j][0] = e0; s[j][1] = e1; s[j][2] = e2; s[j][3] = e3;
                l0 += e0 + e1; l1 += e2 + e3;
            }
        }

        CP_WAIT0();                        // V_it done (only pending group)
        __syncthreads();                   // V visible; all warps past S -> K free
        if (!last) { issue_k(nb, nkb); CP_COMMIT(); }   // K_next overlaps PV

        // ---- O += P V  (full 3-term: Ph*Vh + Pl*Vh + Ph*Vl) ----
#pragma unroll
        for (int kc = 0; kc < 8; ++kc) {
            uint32_t ah[4], al[4];
#pragma unroll
            for (int half = 0; half < 2; ++half) {
                const float* sp = s[2 * kc + half];
                float h0 = __bfloat162float(__float2bfloat16(sp[0]));
                float h1 = __bfloat162float(__float2bfloat16(sp[1]));
                float h2 = __bfloat162float(__float2bfloat16(sp[2]));
                float h3 = __bfloat162float(__float2bfloat16(sp[3]));
                ah[2 * half + 0] = pack_bf16x2(sp[0], sp[1]);
                ah[2 * half + 1] = pack_bf16x2(sp[2], sp[3]);
                al[2 * half + 0] = pack_bf16x2(sp[0] - h0, sp[1] - h1);
                al[2 * half + 1] = pack_bf16x2(sp[2] - h2, sp[3] - h3);
            }
#pragma unroll
            for (int jp = 0; jp < 4; ++jp) {
                uint32_t vh[4], vl[4];
                uint32_t a = sb + STG_VHI + vpat + jp * (16 * 272) + kc * 32;
                ldsm_x4(vh, a);
                ldsm_x4(vl, a + (STG_VLO - STG_VHI));
                mma_bf16(o[2 * jp],     ah, vh[0], vh[1]);
                mma_bf16(o[2 * jp],     al, vh[0], vh[1]);
                mma_bf16(o[2 * jp],     ah, vl[0], vl[1]);
                mma_bf16(o[2 * jp + 1], ah, vh[2], vh[3]);
                mma_bf16(o[2 * jp + 1], al, vh[2], vh[3]);
                mma_bf16(o[2 * jp + 1], ah, vl[2], vl[3]);
            }
        }
        __syncthreads();                   // all warps done reading V
        if (!last) { issue_v(nb, nkb); CP_COMMIT(); }   // V_next overlaps next S

        if (!last && changed) {
            flush(b, qi);
            load_q(nb, nqi);
            __syncthreads();
            build_q();
            zero_acc();
        }
        b = nb; qi = nqi; kb = nkb;
    }
    // final flush: recover the indices of the last computed tile
    {
        int pb = b, pqi = qi;
        if (kb == 0) {
            if (pqi == 0) { --pb; pqi = 64; }
            --pqi;
        }
        flush(pb, pqi);
    }
}

// ===========================================================================
// Kernel 3: normalize — out = O / l   (one float4 per thread, full chip)
// ===========================================================================
__global__ void norm_kernel(float* __restrict__ out)
{
    const int i = blockIdx.x * 256 + threadIdx.x;       // 262144 = NROWS*NH/4
    float4 v = reinterpret_cast<const float4*>(g_oacc)[i];
    float linv = 1.f / g_lacc[i >> 4];
    v.x *= linv; v.y *= linv; v.z *= linv; v.w *= linv;
    reinterpret_cast<float4*>(out)[i] = v;
}

// ===========================================================================
extern "C" void kernel_launch(void* const* d_in, const int* in_sizes, int n_in,
                              void* d_out, int out_size)
{
    (void)in_sizes; (void)n_in; (void)out_size;
    const float* x  = (const float*)d_in[0];
    const float* Wq = (const float*)d_in[1];
    const float* Wk = (const float*)d_in[2];
    const float* Wv = (const float*)d_in[3];
    float* out = (float*)d_out;

    cudaFuncSetAttribute(qkv_mma, cudaFuncAttributeMaxDynamicSharedMemorySize, QS_TOTAL);
    cudaFuncSetAttribute(attn_mma, cudaFuncAttributeMaxDynamicSharedMemorySize, SM_ATT_TOTAL);

    init_kernel<<<512, 256>>>(Wq, Wk, Wv);
    qkv_mma<<<128, 256, QS_TOTAL>>>(x);
    attn_mma<<<296, 128, SM_ATT_TOTAL>>>();
    norm_kernel<<<1024, 256>>>(out);
}

// round 16
// speedup vs baseline: 1.0517x; 1.0517x over previous
#include <cuda_runtime.h>
#include <cuda_bf16.h>
#include <cstdint>

#define NB 4
#define NT 4096
#define NC 1024
#define NH 64
#define NROWS (NB * NT)

// bf16 hi/lo split q, k (row-major [row][h]); v transposed ([b][h][t]).
__device__ __nv_bfloat16 g_qhi[NROWS * NH];
__device__ __nv_bfloat16 g_qlo[NROWS * NH];
__device__ __nv_bfloat16 g_khi[NROWS * NH];
__device__ __nv_bfloat16 g_klo[NROWS * NH];
__device__ __nv_bfloat16 g_vthi[NB * NH * NT];
__device__ __nv_bfloat16 g_vtlo[NB * NH * NT];
// W transposed bf16 hi/lo: [192 cols][1024 c]  (q:0-63, k:64-127, v:128-191)
__device__ __nv_bfloat16 g_wthi[192 * NC];
__device__ __nv_bfloat16 g_wtlo[192 * NC];
// split-K partial accumulators
__device__ float g_oacc[NROWS * NH];
__device__ float g_lacc[NROWS];

// ===========================================================================
// Helpers (sm_80-era PTX: ldmatrix / mma.sync / cp.async — OK in compute_100)
// ===========================================================================
__device__ __forceinline__ uint32_t smem_u32(const void* p) {
    uint32_t a;
    asm("{ .reg .u64 t; cvta.to.shared.u64 t, %1; cvt.u32.u64 %0, t; }"
        : "=r"(a) : "l"(p));
    return a;
}
__device__ __forceinline__ void ldsm_x4(uint32_t* r, uint32_t addr) {
    asm volatile("ldmatrix.sync.aligned.m8n8.x4.shared.b16 {%0,%1,%2,%3}, [%4];"
                 : "=r"(r[0]), "=r"(r[1]), "=r"(r[2]), "=r"(r[3]) : "r"(addr));
}
__device__ __forceinline__ void mma_bf16(float* c, const uint32_t* a,
                                         uint32_t b0, uint32_t b1) {
    asm volatile(
        "mma.sync.aligned.m16n8k16.row.col.f32.bf16.bf16.f32 "
        "{%0,%1,%2,%3}, {%4,%5,%6,%7}, {%8,%9}, {%0,%1,%2,%3};"
        : "+f"(c[0]), "+f"(c[1]), "+f"(c[2]), "+f"(c[3])
        : "r"(a[0]), "r"(a[1]), "r"(a[2]), "r"(a[3]), "r"(b0), "r"(b1));
}
__device__ __forceinline__ uint32_t pack_bf16x2(float lo, float hi) {
    uint32_t r;
    asm("cvt.rn.bf16x2.f32 %0, %1, %2;" : "=r"(r) : "f"(hi), "f"(lo));
    return r;
}
#define CP16(dst, src) \
    asm volatile("cp.async.cg.shared.global [%0], [%1], 16;" :: "r"(dst), "l"(src))
#define CP_COMMIT() asm volatile("cp.async.commit_group;" ::: "memory")
#define CP_WAIT0()  asm volatile("cp.async.wait_group 0;" ::: "memory")
#define CP_WAIT1()  asm volatile("cp.async.wait_group 1;" ::: "memory")

// ===========================================================================
// Kernel 0: init — zero split-K accumulators; build transposed bf16 hi/lo W.
// ===========================================================================
__global__ void init_kernel(const float* __restrict__ Wq,
                            const float* __restrict__ Wk,
                            const float* __restrict__ Wv)
{
    const int tid = blockIdx.x * 256 + threadIdx.x;   // 0..131071
    float4 z = make_float4(0.f, 0.f, 0.f, 0.f);
#pragma unroll
    for (int i = tid; i < (NROWS * NH) / 4; i += 131072)
        reinterpret_cast<float4*>(g_oacc)[i] = z;
    if (tid < NROWS) g_lacc[tid] = 0.f;

    if (tid < 65536) {
        const int c = tid >> 6;      // 0..1023
        const int h = tid & 63;
        float wq = Wq[c * NH + h], wk = Wk[c * NH + h], wv = Wv[c * NH + h];
        __nv_bfloat16 h0 = __float2bfloat16(wq);
        __nv_bfloat16 h1 = __float2bfloat16(wk);
        __nv_bfloat16 h2 = __float2bfloat16(wv);
        g_wthi[(h)       * NC + c] = h0;
        g_wthi[(64 + h)  * NC + c] = h1;
        g_wthi[(128 + h) * NC + c] = h2;
        g_wtlo[(h)       * NC + c] = __float2bfloat16(wq - __bfloat162float(h0));
        g_wtlo[(64 + h)  * NC + c] = __float2bfloat16(wk - __bfloat162float(h1));
        g_wtlo[(128 + h) * NC + c] = __float2bfloat16(wv - __bfloat162float(h2));
    }
}

// ===========================================================================
// Kernel 1: QKV projection via mma.sync bf16 3-term split (exact R13 winner).
// ===========================================================================
#define QS_XSTG 36864
#define QS_W    73728
#define QS_WSTG 55296
#define QS_TOTAL (QS_W + 2 * QS_WSTG)  // 184320 B

__global__ __launch_bounds__(256, 1)
void qkv_mma(const float* __restrict__ x)
{
    extern __shared__ char smem[];
    const uint32_t sb = smem_u32(smem);
    const int t    = threadIdx.x;
    const int w    = t >> 5;
    const int lane = t & 31;
    const int wm   = w & 3;
    const int wn   = w >> 2;
    const int row0 = blockIdx.x * 128;

    float acc[2][12][4];
#pragma unroll
    for (int mt = 0; mt < 2; ++mt)
#pragma unroll
        for (int j = 0; j < 12; ++j)
#pragma unroll
            for (int c = 0; c < 4; ++c) acc[mt][j][c] = 0.f;

    const uint32_t apat = (32 * wm + (lane & 15)) * 144 + (lane >> 4) * 16;
    const uint32_t bpat = ((96 * wn + ((lane >> 4) << 3) + (lane & 7)) * 144) +
                          ((lane >> 3) & 1) * 16;

    float4 xreg[8];
    auto load_x = [&](int c0) {
#pragma unroll
        for (int it = 0; it < 8; ++it) {
            int i   = t + it * 256;
            int row = i >> 4;
            int c4  = (i & 15) * 4;
            xreg[it] = *reinterpret_cast<const float4*>(
                x + (size_t)(row0 + row) * NC + c0 + c4);
        }
    };
    auto store_x = [&](int stage) {
        char* xb = smem + stage * QS_XSTG;
#pragma unroll
        for (int it = 0; it < 8; ++it) {
            int i   = t + it * 256;
            int row = i >> 4;
            int c4  = (i & 15) * 4;
            float4 v = xreg[it];
            float hx = __bfloat162float(__float2bfloat16(v.x));
            float hy = __bfloat162float(__float2bfloat16(v.y));
            float hz = __bfloat162float(__float2bfloat16(v.z));
            float hw = __bfloat162float(__float2bfloat16(v.w));
            uint2 hi2 = make_uint2(pack_bf16x2(v.x, v.y), pack_bf16x2(v.z, v.w));
            uint2 lo2 = make_uint2(pack_bf16x2(v.x - hx, v.y - hy),
                                   pack_bf16x2(v.z - hz, v.w - hw));
            uint32_t doff = row * 144 + c4 * 2;
            *reinterpret_cast<uint2*>(xb + doff)         = hi2;
            *reinterpret_cast<uint2*>(xb + 18432 + doff) = lo2;
        }
    };
    auto issue_w = [&](int stage, int c0) {
        uint32_t st = sb + QS_W + stage * QS_WSTG;
#pragma unroll
        for (int it = 0; it < 6; ++it) {
            int i   = t + it * 256;
            int col = i >> 3;
            int c8  = (i & 7) * 8;
            uint32_t doff = col * 144 + c8 * 2;
            CP16(st + doff,         g_wthi + (size_t)col * NC + c0 + c8);
            CP16(st + 27648 + doff, g_wtlo + (size_t)col * NC + c0 + c8);
        }
    };

    issue_w(0, 0);
    CP_COMMIT();
    load_x(0);
    store_x(0);
    load_x(64);

    for (int c = 0; c < 16; ++c) {
        __syncthreads();
        if (c < 15) { issue_w((c + 1) & 1, (c + 1) * 64); CP_COMMIT(); }
        if (c < 15) { CP_WAIT1(); } else { CP_WAIT0(); }
        __syncthreads();

        const uint32_t xst = sb + (c & 1) * QS_XSTG;
        const uint32_t wst = sb + QS_W + (c & 1) * QS_WSTG;
        uint32_t ah[2][4][4], al[2][4][4];
#pragma unroll
        for (int mt = 0; mt < 2; ++mt)
#pragma unroll
            for (int ks = 0; ks < 4; ++ks) {
                uint32_t a = xst + apat + mt * (16 * 144) + ks * 32;
                ldsm_x4(ah[mt][ks], a);
                ldsm_x4(al[mt][ks], a + 18432);
            }
#pragma unroll
        for (int n2 = 0; n2 < 6; ++n2) {
#pragma unroll
            for (int ks = 0; ks < 4; ++ks) {
                uint32_t bh[4], bl[4];
                uint32_t a = wst + bpat + n2 * (16 * 144) + ks * 32;
                ldsm_x4(bh, a);
                ldsm_x4(bl, a + 27648);
#pragma unroll
                for (int mt = 0; mt < 2; ++mt) {
                    float* cA = acc[mt][2 * n2];
                    float* cB = acc[mt][2 * n2 + 1];
                    mma_bf16(cA, ah[mt][ks], bh[0], bh[1]);
                    mma_bf16(cA, ah[mt][ks], bl[0], bl[1]);
                    mma_bf16(cA, al[mt][ks], bh[0], bh[1]);
                    mma_bf16(cB, ah[mt][ks], bh[2], bh[3]);
                    mma_bf16(cB, ah[mt][ks], bl[2], bl[3]);
                    mma_bf16(cB, al[mt][ks], bh[2], bh[3]);
                }
            }
        }
        if (c < 15) {
            store_x((c + 1) & 1);
            if (c < 14) load_x((c + 2) * 64);
        }
    }

#pragma unroll
    for (int mt = 0; mt < 2; ++mt) {
        const int ra = row0 + 32 * wm + 16 * mt + (lane >> 2);
#pragma unroll
        for (int j = 0; j < 12; ++j) {
            int col = 96 * wn + 8 * j + 2 * (lane & 3);
#pragma unroll
            for (int half = 0; half < 2; ++half) {
                int row = ra + 8 * half;
                float v0 = acc[mt][j][2 * half], v1 = acc[mt][j][2 * half + 1];
                float h0 = __bfloat162float(__float2bfloat16(v0));
                float h1 = __bfloat162float(__float2bfloat16(v1));
                uint32_t hi = pack_bf16x2(v0, v1);
                uint32_t lo = pack_bf16x2(v0 - h0, v1 - h1);
                if (col < 64) {
                    *reinterpret_cast<uint32_t*>(g_qhi + (size_t)row * NH + col) = hi;
                    *reinterpret_cast<uint32_t*>(g_qlo + (size_t)row * NH + col) = lo;
                } else if (col < 128) {
                    *reinterpret_cast<uint32_t*>(g_khi + (size_t)row * NH + col - 64) = hi;
                    *reinterpret_cast<uint32_t*>(g_klo + (size_t)row * NH + col - 64) = lo;
                } else {
                    int h  = col - 128;
                    int bb = row >> 12, tt = row & (NT - 1);
                    size_t i0 = ((size_t)bb * NH + h) * NT + tt;
                    g_vthi[i0]      = __float2bfloat16(v0);
                    g_vtlo[i0]      = __float2bfloat16(v0 - h0);
                    g_vthi[i0 + NT] = __float2bfloat16(v1);
                    g_vtlo[i0 + NT] = __float2bfloat16(v1 - h1);
                }
            }
        }
    }
}

// ===========================================================================
// Kernel 2: balanced split-K causal attention — NEW 128q x 64k tile aspect.
// 128 threads (4 warps): warp w owns q-rows [32w, 32w+32) (2 m-tiles) and
// ALL 64 keys -> every K/V fragment feeds 2 m-tiles (B-side ldsm halved:
// 64/warp/tile at the same 384 MMAs -> smem crossbar pressure ~halved).
// Double-buffered 36KB K/V stages, 2 CTAs/SM, 1 sync/tile.
// Q fragments re-ldsm'd per tile (keeps regs ~210, no spill risk).
// ===========================================================================
#define AST_KHI 0
#define AST_KLO 9216
#define AST_VHI 18432
#define AST_VLO 27648
#define AST_SZ  36864
#define SM_Q_HI (2 * AST_SZ)            // 73728
#define SM_Q_LO (SM_Q_HI + 18432)
#define SM_ATT_TOTAL (SM_Q_LO + 18432)  // 110592 B

__global__ __launch_bounds__(128, 2)
void attn_mma()
{
    extern __shared__ char smem[];
    const uint32_t sb = smem_u32(smem);
    const int t    = threadIdx.x;
    const int w    = t >> 5;          // 0..3
    const int lane = t & 31;

    // ---- linear tile range: per b, q-tiles qi 0..31 (128 rows),
    //      k-tiles kb 0..2qi+1 (64 keys). 1056 tiles per b, 4224 total.
    const int bid = blockIdx.x;
    int g0  = bid * 14 + (bid < 80 ? bid : 80);
    int cnt = 14 + (bid < 80 ? 1 : 0);

    int b = g0 / 1056;
    int r = g0 % 1056;
    int qi = 0, cum = 0;
    while (cum + 2 * qi + 2 <= r) { cum += 2 * qi + 2; ++qi; }
    int kb = r - cum;

    const uint32_t kpat = ((((lane >> 4) << 3) + (lane & 7)) * 144) +
                          ((lane >> 3) & 1) * 16;
    const uint32_t vpat = kpat;           // V stride is also 144 now
    const uint32_t qpat = (32 * w + (lane & 15)) * 144 + (lane >> 4) * 16;

    auto issue_kv = [&](int stage, int bb, int kbb) {
        uint32_t st = sb + stage * AST_SZ;
        int k0 = kbb * 64;
        const __nv_bfloat16* kh = g_khi + ((size_t)bb * NT + k0) * NH;
        const __nv_bfloat16* kl = g_klo + ((size_t)bb * NT + k0) * NH;
#pragma unroll
        for (int it = 0; it < 4; ++it) {
            int i   = t + it * 128;        // 0..511
            int row = i >> 3;              // 0..63 (key)
            int c8  = (i & 7) * 8;         // h
            uint32_t doff = row * 144 + c8 * 2;
            CP16(st + AST_KHI + doff, kh + row * NH + c8);
            CP16(st + AST_KLO + doff, kl + row * NH + c8);
        }
        const __nv_bfloat16* vh = g_vthi + (size_t)bb * NH * NT + k0;
        const __nv_bfloat16* vl = g_vtlo + (size_t)bb * NH * NT + k0;
#pragma unroll
        for (int it = 0; it < 4; ++it) {
            int i  = t + it * 128;
            int h  = i >> 3;               // 0..63
            int k8 = (i & 7) * 8;          // key
            uint32_t doff = h * 144 + k8 * 2;
            CP16(st + AST_VHI + doff, vh + (size_t)h * NT + k8);
            CP16(st + AST_VLO + doff, vl + (size_t)h * NT + k8);
        }
    };
    auto load_q = [&](int bb, int qii) {
        const __nv_bfloat16* qh = g_qhi + ((size_t)bb * NT + qii * 128) * NH;
        const __nv_bfloat16* ql = g_qlo + ((size_t)bb * NT + qii * 128) * NH;
#pragma unroll
        for (int it = 0; it < 8; ++it) {
            int i   = t + it * 128;        // 0..1023
            int row = i >> 3;              // 0..127
            int c8  = (i & 7) * 8;
            uint32_t doff = row * 144 + c8 * 2;
            *reinterpret_cast<uint4*>(smem + SM_Q_HI + doff) =
                *reinterpret_cast<const uint4*>(qh + row * NH + c8);
            *reinterpret_cast<uint4*>(smem + SM_Q_LO + doff) =
                *reinterpret_cast<const uint4*>(ql + row * NH + c8);
        }
    };

    float o[2][8][4], l[2][2];
    auto zero_acc = [&]() {
#pragma unroll
        for (int mt = 0; mt < 2; ++mt) {
#pragma unroll
            for (int j = 0; j < 8; ++j)
#pragma unroll
                for (int c = 0; c < 4; ++c) o[mt][j][c] = 0.f;
            l[mt][0] = l[mt][1] = 0.f;
        }
    };
    auto flush = [&](int bb, int qii) {
#pragma unroll
        for (int mt = 0; mt < 2; ++mt) {
            float r0 = l[mt][0], r1 = l[mt][1];
            r0 += __shfl_xor_sync(0xffffffffu, r0, 1);
            r0 += __shfl_xor_sync(0xffffffffu, r0, 2);
            r1 += __shfl_xor_sync(0xffffffffu, r1, 1);
            r1 += __shfl_xor_sync(0xffffffffu, r1, 2);
            int rra = bb * NT + qii * 128 + 32 * w + 16 * mt + (lane >> 2);
            if ((lane & 3) == 0) {
                atomicAdd(&g_lacc[rra], r0);
                atomicAdd(&g_lacc[rra + 8], r1);
            }
            float* o0 = g_oacc + (size_t)rra * NH;
            float* o1 = g_oacc + (size_t)(rra + 8) * NH;
#pragma unroll
            for (int j = 0; j < 8; ++j) {
                int h = 8 * j + 2 * (lane & 3);
                atomicAdd(o0 + h,     o[mt][j][0]);
                atomicAdd(o0 + h + 1, o[mt][j][1]);
                atomicAdd(o1 + h,     o[mt][j][2]);
                atomicAdd(o1 + h + 1, o[mt][j][3]);
            }
        }
    };

    // ---- prologue ----
    issue_kv(0, b, kb);
    CP_COMMIT();
    load_q(b, qi);
    __syncthreads();
    zero_acc();

    for (int it = 0; it < cnt; ++it) {
        int nb = b, nqi = qi, nkb = kb + 1;
        bool changed = false;
        if (nkb > 2 * qi + 1) {
            nkb = 0; ++nqi; changed = true;
            if (nqi == 32) { nqi = 0; ++nb; }
        }
        const bool last = (it == cnt - 1);

        CP_WAIT0();                        // stage (it&1) data arrived
        __syncthreads();                   // visible; prior compute done -> other
                                           // stage free for refill
        if (!last) { issue_kv((it + 1) & 1, nb, nkb); CP_COMMIT(); }

        const uint32_t st = sb + (it & 1) * AST_SZ;
        const int k0 = kb * 64;
        const int q0 = qi * 128;
        const bool diag = (kb >= 2 * qi);  // last two k-tiles need masking

        // ---- Q fragments for this warp (2 m-tiles x 4 ks, hi/lo) ----
        uint32_t qh[2][4][4], ql[2][4][4];
#pragma unroll
        for (int mt = 0; mt < 2; ++mt)
#pragma unroll
            for (int ks = 0; ks < 4; ++ks) {
                uint32_t a = sb + SM_Q_HI + qpat + mt * (16 * 144) + ks * 32;
                ldsm_x4(qh[mt][ks], a);
                ldsm_x4(ql[mt][ks], a + 18432);
            }

        // ---- S = Q K^T : shared K fragments feed both m-tiles ----
        float s[2][8][4];
#pragma unroll
        for (int mt = 0; mt < 2; ++mt)
#pragma unroll
            for (int j = 0; j < 8; ++j)
#pragma unroll
                for (int c = 0; c < 4; ++c) s[mt][j][c] = 0.f;
#pragma unroll
        for (int j2 = 0; j2 < 4; ++j2) {
#pragma unroll
            for (int ks = 0; ks < 4; ++ks) {
                uint32_t kh[4], kl[4];
                uint32_t a = st + kpat + j2 * (16 * 144) + ks * 32;
                ldsm_x4(kh, a + AST_KHI);
                ldsm_x4(kl, a + (AST_KLO - AST_KHI) + AST_KHI);  // + 9216
#pragma unroll
                for (int mt = 0; mt < 2; ++mt) {
                    float* sA = s[mt][2 * j2];
                    float* sB = s[mt][2 * j2 + 1];
                    mma_bf16(sA, qh[mt][ks], kh[0], kh[1]);
                    mma_bf16(sA, qh[mt][ks], kl[0], kl[1]);
                    mma_bf16(sA, ql[mt][ks], kh[0], kh[1]);
                    mma_bf16(sB, qh[mt][ks], kh[2], kh[3]);
                    mma_bf16(sB, qh[mt][ks], kl[2], kl[3]);
                    mma_bf16(sB, ql[mt][ks], kh[2], kh[3]);
                }
            }
        }

        // ---- exp (+ causal mask on diagonal tiles) ----
#pragma unroll
        for (int mt = 0; mt < 2; ++mt) {
            const int ra = q0 + 32 * w + 16 * mt + (lane >> 2);
            if (diag) {
#pragma unroll
                for (int j = 0; j < 8; ++j) {
                    int col = k0 + 8 * j + 2 * (lane & 3);
                    float e0 = (col     <= ra)     ? __expf(s[mt][j][0]) : 0.f;
                    float e1 = (col + 1 <= ra)     ? __expf(s[mt][j][1]) : 0.f;
                    float e2 = (col     <= ra + 8) ? __expf(s[mt][j][2]) : 0.f;
                    float e3 = (col + 1 <= ra + 8) ? __expf(s[mt][j][3]) : 0.f;
                    s[mt][j][0] = e0; s[mt][j][1] = e1;
                    s[mt][j][2] = e2; s[mt][j][3] = e3;
                    l[mt][0] += e0 + e1; l[mt][1] += e2 + e3;
                }
            } else {
#pragma unroll
                for (int j = 0; j < 8; ++j) {
                    float e0 = __expf(s[mt][j][0]);
                    float e1 = __expf(s[mt][j][1]);
                    float e2 = __expf(s[mt][j][2]);
                    float e3 = __expf(s[mt][j][3]);
                    s[mt][j][0] = e0; s[mt][j][1] = e1;
                    s[mt][j][2] = e2; s[mt][j][3] = e3;
                    l[mt][0] += e0 + e1; l[mt][1] += e2 + e3;
                }
            }
        }

        // ---- O += P V : shared V fragments feed both m-tiles ----
#pragma unroll
        for (int kc = 0; kc < 4; ++kc) {
            uint32_t ah[2][4], al[2][4];
#pragma unroll
            for (int mt = 0; mt < 2; ++mt)
#pragma unroll
                for (int half = 0; half < 2; ++half) {
                    const float* sp = s[mt][2 * kc + half];
                    float h0 = __bfloat162float(__float2bfloat16(sp[0]));
                    float h1 = __bfloat162float(__float2bfloat16(sp[1]));
                    float h2 = __bfloat162float(__float2bfloat16(sp[2]));
                    float h3 = __bfloat162float(__float2bfloat16(sp[3]));
                    ah[mt][2 * half + 0] = pack_bf16x2(sp[0], sp[1]);
                    ah[mt][2 * half + 1] = pack_bf16x2(sp[2], sp[3]);
                    al[mt][2 * half + 0] = pack_bf16x2(sp[0] - h0, sp[1] - h1);
                    al[mt][2 * half + 1] = pack_bf16x2(sp[2] - h2, sp[3] - h3);
                }
#pragma unroll
            for (int jp = 0; jp < 4; ++jp) {
                uint32_t vh[4], vl[4];
                uint32_t a = st + AST_VHI + vpat + jp * (16 * 144) + kc * 32;
                ldsm_x4(vh, a);
                ldsm_x4(vl, a + (AST_VLO - AST_VHI));
#pragma unroll
                for (int mt = 0; mt < 2; ++mt) {
                    mma_bf16(o[mt][2 * jp],     ah[mt], vh[0], vh[1]);
                    mma_bf16(o[mt][2 * jp],     al[mt], vh[0], vh[1]);
                    mma_bf16(o[mt][2 * jp],     ah[mt], vl[0], vl[1]);
                    mma_bf16(o[mt][2 * jp + 1], ah[mt], vh[2], vh[3]);
                    mma_bf16(o[mt][2 * jp + 1], al[mt], vh[2], vh[3]);
                    mma_bf16(o[mt][2 * jp + 1], ah[mt], vl[2], vl[3]);
                }
            }
        }

        if (!last && changed) {
            flush(b, qi);
            load_q(nb, nqi);
            zero_acc();
        }
        b = nb; qi = nqi; kb = nkb;
    }
    // final flush: recover indices of the last computed tile
    {
        int pb = b, pqi = qi;
        if (kb == 0) {
            if (pqi == 0) { --pb; pqi = 32; }
            --pqi;
        }
        flush(pb, pqi);
    }
}

// ===========================================================================
// Kernel 3: normalize — out = O / l   (one float4 per thread, full chip)
// ===========================================================================
__global__ void norm_kernel(float* __restrict__ out)
{
    const int i = blockIdx.x * 256 + threadIdx.x;       // 262144 = NROWS*NH/4
    float4 v = reinterpret_cast<const float4*>(g_oacc)[i];
    float linv = 1.f / g_lacc[i >> 4];
    v.x *= linv; v.y *= linv; v.z *= linv; v.w *= linv;
    reinterpret_cast<float4*>(out)[i] = v;
}

// ===========================================================================
extern "C" void kernel_launch(void* const* d_in, const int* in_sizes, int n_in,
                              void* d_out, int out_size)
{
    (void)in_sizes; (void)n_in; (void)out_size;
    const float* x  = (const float*)d_in[0];
    const float* Wq = (const float*)d_in[1];
    const float* Wk = (const float*)d_in[2];
    const float* Wv = (const float*)d_in[3];
    float* out = (float*)d_out;

    cudaFuncSetAttribute(qkv_mma, cudaFuncAttributeMaxDynamicSharedMemorySize, QS_TOTAL);
    cudaFuncSetAttribute(attn_mma, cudaFuncAttributeMaxDynamicSharedMemorySize, SM_ATT_TOTAL);

    init_kernel<<<512, 256>>>(Wq, Wk, Wv);
    qkv_mma<<<128, 256, QS_TOTAL>>>(x);
    attn_mma<<<296, 128, SM_ATT_TOTAL>>>();
    norm_kernel<<<1024, 256>>>(out);
}

// round 17
// speedup vs baseline: 1.0625x; 1.0103x over previous
#include <cuda_runtime.h>
#include <cuda_bf16.h>
#include <cstdint>

#define NB 4
#define NT 4096
#define NC 1024
#define NH 64
#define NROWS (NB * NT)
#define LOG2E 1.4426950408889634f

// bf16 hi/lo split q (PRE-SCALED by log2e), k (row-major [row][h]);
// v transposed ([b][h][t]).
__device__ __nv_bfloat16 g_qhi[NROWS * NH];
__device__ __nv_bfloat16 g_qlo[NROWS * NH];
__device__ __nv_bfloat16 g_khi[NROWS * NH];
__device__ __nv_bfloat16 g_klo[NROWS * NH];
__device__ __nv_bfloat16 g_vthi[NB * NH * NT];
__device__ __nv_bfloat16 g_vtlo[NB * NH * NT];
// W transposed bf16 hi/lo: [192 cols][1024 c]  (q:0-63, k:64-127, v:128-191)
__device__ __nv_bfloat16 g_wthi[192 * NC];
__device__ __nv_bfloat16 g_wtlo[192 * NC];
// split-K partial accumulators
__device__ float g_oacc[NROWS * NH];
__device__ float g_lacc[NROWS];

// ===========================================================================
// Helpers (sm_80-era PTX: ldmatrix / mma.sync / cp.async — OK in compute_100)
// ===========================================================================
__device__ __forceinline__ uint32_t smem_u32(const void* p) {
    uint32_t a;
    asm("{ .reg .u64 t; cvta.to.shared.u64 t, %1; cvt.u32.u64 %0, t; }"
        : "=r"(a) : "l"(p));
    return a;
}
__device__ __forceinline__ void ldsm_x4(uint32_t* r, uint32_t addr) {
    asm volatile("ldmatrix.sync.aligned.m8n8.x4.shared.b16 {%0,%1,%2,%3}, [%4];"
                 : "=r"(r[0]), "=r"(r[1]), "=r"(r[2]), "=r"(r[3]) : "r"(addr));
}
__device__ __forceinline__ void mma_bf16(float* c, const uint32_t* a,
                                         uint32_t b0, uint32_t b1) {
    asm volatile(
        "mma.sync.aligned.m16n8k16.row.col.f32.bf16.bf16.f32 "
        "{%0,%1,%2,%3}, {%4,%5,%6,%7}, {%8,%9}, {%0,%1,%2,%3};"
        : "+f"(c[0]), "+f"(c[1]), "+f"(c[2]), "+f"(c[3])
        : "r"(a[0]), "r"(a[1]), "r"(a[2]), "r"(a[3]), "r"(b0), "r"(b1));
}
__device__ __forceinline__ uint32_t pack_bf16x2(float lo, float hi) {
    uint32_t r;
    asm("cvt.rn.bf16x2.f32 %0, %1, %2;" : "=r"(r) : "f"(hi), "f"(lo));
    return r;
}
__device__ __forceinline__ float ex2f(float x) {
    float y;
    asm("ex2.approx.f32 %0, %1;" : "=f"(y) : "f"(x));
    return y;
}
#define CP16(dst, src) \
    asm volatile("cp.async.cg.shared.global [%0], [%1], 16;" :: "r"(dst), "l"(src))
#define CP_COMMIT() asm volatile("cp.async.commit_group;" ::: "memory")
#define CP_WAIT0()  asm volatile("cp.async.wait_group 0;" ::: "memory")
#define CP_WAIT1()  asm volatile("cp.async.wait_group 1;" ::: "memory")

// ===========================================================================
// Kernel 0: init — zero split-K accumulators; build transposed bf16 hi/lo W.
// ===========================================================================
__global__ void init_kernel(const float* __restrict__ Wq,
                            const float* __restrict__ Wk,
                            const float* __restrict__ Wv)
{
    const int tid = blockIdx.x * 256 + threadIdx.x;   // 0..131071
    float4 z = make_float4(0.f, 0.f, 0.f, 0.f);
#pragma unroll
    for (int i = tid; i < (NROWS * NH) / 4; i += 131072)
        reinterpret_cast<float4*>(g_oacc)[i] = z;
    if (tid < NROWS) g_lacc[tid] = 0.f;

    if (tid < 65536) {
        const int c = tid >> 6;      // 0..1023
        const int h = tid & 63;
        float wq = Wq[c * NH + h], wk = Wk[c * NH + h], wv = Wv[c * NH + h];
        __nv_bfloat16 h0 = __float2bfloat16(wq);
        __nv_bfloat16 h1 = __float2bfloat16(wk);
        __nv_bfloat16 h2 = __float2bfloat16(wv);
        g_wthi[(h)       * NC + c] = h0;
        g_wthi[(64 + h)  * NC + c] = h1;
        g_wthi[(128 + h) * NC + c] = h2;
        g_wtlo[(h)       * NC + c] = __float2bfloat16(wq - __bfloat162float(h0));
        g_wtlo[(64 + h)  * NC + c] = __float2bfloat16(wk - __bfloat162float(h1));
        g_wtlo[(128 + h) * NC + c] = __float2bfloat16(wv - __bfloat162float(h2));
    }
}

// ===========================================================================
// Kernel 1: QKV projection via mma.sync bf16 3-term split (R13 winner).
// NEW: q outputs are pre-scaled by log2e so attention can use bare ex2.
// ===========================================================================
#define QS_XSTG 36864
#define QS_W    73728
#define QS_WSTG 55296
#define QS_TOTAL (QS_W + 2 * QS_WSTG)  // 184320 B

__global__ __launch_bounds__(256, 1)
void qkv_mma(const float* __restrict__ x)
{
    extern __shared__ char smem[];
    const uint32_t sb = smem_u32(smem);
    const int t    = threadIdx.x;
    const int w    = t >> 5;
    const int lane = t & 31;
    const int wm   = w & 3;
    const int wn   = w >> 2;
    const int row0 = blockIdx.x * 128;

    float acc[2][12][4];
#pragma unroll
    for (int mt = 0; mt < 2; ++mt)
#pragma unroll
        for (int j = 0; j < 12; ++j)
#pragma unroll
            for (int c = 0; c < 4; ++c) acc[mt][j][c] = 0.f;

    const uint32_t apat = (32 * wm + (lane & 15)) * 144 + (lane >> 4) * 16;
    const uint32_t bpat = ((96 * wn + ((lane >> 4) << 3) + (lane & 7)) * 144) +
                          ((lane >> 3) & 1) * 16;

    float4 xreg[8];
    auto load_x = [&](int c0) {
#pragma unroll
        for (int it = 0; it < 8; ++it) {
            int i   = t + it * 256;
            int row = i >> 4;
            int c4  = (i & 15) * 4;
            xreg[it] = *reinterpret_cast<const float4*>(
                x + (size_t)(row0 + row) * NC + c0 + c4);
        }
    };
    auto store_x = [&](int stage) {
        char* xb = smem + stage * QS_XSTG;
#pragma unroll
        for (int it = 0; it < 8; ++it) {
            int i   = t + it * 256;
            int row = i >> 4;
            int c4  = (i & 15) * 4;
            float4 v = xreg[it];
            float hx = __bfloat162float(__float2bfloat16(v.x));
            float hy = __bfloat162float(__float2bfloat16(v.y));
            float hz = __bfloat162float(__float2bfloat16(v.z));
            float hw = __bfloat162float(__float2bfloat16(v.w));
            uint2 hi2 = make_uint2(pack_bf16x2(v.x, v.y), pack_bf16x2(v.z, v.w));
            uint2 lo2 = make_uint2(pack_bf16x2(v.x - hx, v.y - hy),
                                   pack_bf16x2(v.z - hz, v.w - hw));
            uint32_t doff = row * 144 + c4 * 2;
            *reinterpret_cast<uint2*>(xb + doff)         = hi2;
            *reinterpret_cast<uint2*>(xb + 18432 + doff) = lo2;
        }
    };
    auto issue_w = [&](int stage, int c0) {
        uint32_t st = sb + QS_W + stage * QS_WSTG;
#pragma unroll
        for (int it = 0; it < 6; ++it) {
            int i   = t + it * 256;
            int col = i >> 3;
            int c8  = (i & 7) * 8;
            uint32_t doff = col * 144 + c8 * 2;
            CP16(st + doff,         g_wthi + (size_t)col * NC + c0 + c8);
            CP16(st + 27648 + doff, g_wtlo + (size_t)col * NC + c0 + c8);
        }
    };

    issue_w(0, 0);
    CP_COMMIT();
    load_x(0);
    store_x(0);
    load_x(64);

    for (int c = 0; c < 16; ++c) {
        __syncthreads();
        if (c < 15) { issue_w((c + 1) & 1, (c + 1) * 64); CP_COMMIT(); }
        if (c < 15) { CP_WAIT1(); } else { CP_WAIT0(); }
        __syncthreads();

        const uint32_t xst = sb + (c & 1) * QS_XSTG;
        const uint32_t wst = sb + QS_W + (c & 1) * QS_WSTG;
        uint32_t ah[2][4][4], al[2][4][4];
#pragma unroll
        for (int mt = 0; mt < 2; ++mt)
#pragma unroll
            for (int ks = 0; ks < 4; ++ks) {
                uint32_t a = xst + apat + mt * (16 * 144) + ks * 32;
                ldsm_x4(ah[mt][ks], a);
                ldsm_x4(al[mt][ks], a + 18432);
            }
#pragma unroll
        for (int n2 = 0; n2 < 6; ++n2) {
#pragma unroll
            for (int ks = 0; ks < 4; ++ks) {
                uint32_t bh[4], bl[4];
                uint32_t a = wst + bpat + n2 * (16 * 144) + ks * 32;
                ldsm_x4(bh, a);
                ldsm_x4(bl, a + 27648);
#pragma unroll
                for (int mt = 0; mt < 2; ++mt) {
                    float* cA = acc[mt][2 * n2];
                    float* cB = acc[mt][2 * n2 + 1];
                    mma_bf16(cA, ah[mt][ks], bh[0], bh[1]);
                    mma_bf16(cA, ah[mt][ks], bl[0], bl[1]);
                    mma_bf16(cA, al[mt][ks], bh[0], bh[1]);
                    mma_bf16(cB, ah[mt][ks], bh[2], bh[3]);
                    mma_bf16(cB, ah[mt][ks], bl[2], bl[3]);
                    mma_bf16(cB, al[mt][ks], bh[2], bh[3]);
                }
            }
        }
        if (c < 15) {
            store_x((c + 1) & 1);
            if (c < 14) load_x((c + 2) * 64);
        }
    }

#pragma unroll
    for (int mt = 0; mt < 2; ++mt) {
        const int ra = row0 + 32 * wm + 16 * mt + (lane >> 2);
#pragma unroll
        for (int j = 0; j < 12; ++j) {
            int col = 96 * wn + 8 * j + 2 * (lane & 3);
#pragma unroll
            for (int half = 0; half < 2; ++half) {
                int row = ra + 8 * half;
                float v0 = acc[mt][j][2 * half], v1 = acc[mt][j][2 * half + 1];
                if (col < 64) { v0 *= LOG2E; v1 *= LOG2E; }   // fold exp's log2e
                float h0 = __bfloat162float(__float2bfloat16(v0));
                float h1 = __bfloat162float(__float2bfloat16(v1));
                uint32_t hi = pack_bf16x2(v0, v1);
                uint32_t lo = pack_bf16x2(v0 - h0, v1 - h1);
                if (col < 64) {
                    *reinterpret_cast<uint32_t*>(g_qhi + (size_t)row * NH + col) = hi;
                    *reinterpret_cast<uint32_t*>(g_qlo + (size_t)row * NH + col) = lo;
                } else if (col < 128) {
                    *reinterpret_cast<uint32_t*>(g_khi + (size_t)row * NH + col - 64) = hi;
                    *reinterpret_cast<uint32_t*>(g_klo + (size_t)row * NH + col - 64) = lo;
                } else {
                    int h  = col - 128;
                    int bb = row >> 12, tt = row & (NT - 1);
                    size_t i0 = ((size_t)bb * NH + h) * NT + tt;
                    g_vthi[i0]      = __float2bfloat16(v0);
                    g_vtlo[i0]      = __float2bfloat16(v0 - h0);
                    g_vthi[i0 + NT] = __float2bfloat16(v1);
                    g_vtlo[i0 + NT] = __float2bfloat16(v1 - h1);
                }
            }
        }
    }
}

// ===========================================================================
// Kernel 2: balanced split-K causal attention — 128q x 64k tiles (R16 winner)
// + Q fragments cached in registers across k-tiles (rebuilt only on q-tile
// change) + bare ex2 (log2e folded into q at projection).
// ===========================================================================
#define AST_KHI 0
#define AST_KLO 9216
#define AST_VHI 18432
#define AST_VLO 27648
#define AST_SZ  36864
#define SM_Q_HI (2 * AST_SZ)            // 73728
#define SM_Q_LO (SM_Q_HI + 18432)
#define SM_ATT_TOTAL (SM_Q_LO + 18432)  // 110592 B

__global__ __launch_bounds__(128, 2)
void attn_mma()
{
    extern __shared__ char smem[];
    const uint32_t sb = smem_u32(smem);
    const int t    = threadIdx.x;
    const int w    = t >> 5;          // 0..3
    const int lane = t & 31;

    const int bid = blockIdx.x;
    int g0  = bid * 14 + (bid < 80 ? bid : 80);
    int cnt = 14 + (bid < 80 ? 1 : 0);

    int b = g0 / 1056;
    int r = g0 % 1056;
    int qi = 0, cum = 0;
    while (cum + 2 * qi + 2 <= r) { cum += 2 * qi + 2; ++qi; }
    int kb = r - cum;

    const uint32_t kpat = ((((lane >> 4) << 3) + (lane & 7)) * 144) +
                          ((lane >> 3) & 1) * 16;
    const uint32_t vpat = kpat;
    const uint32_t qpat = (32 * w + (lane & 15)) * 144 + (lane >> 4) * 16;

    auto issue_kv = [&](int stage, int bb, int kbb) {
        uint32_t st = sb + stage * AST_SZ;
        int k0 = kbb * 64;
        const __nv_bfloat16* kh = g_khi + ((size_t)bb * NT + k0) * NH;
        const __nv_bfloat16* kl = g_klo + ((size_t)bb * NT + k0) * NH;
#pragma unroll
        for (int it = 0; it < 4; ++it) {
            int i   = t + it * 128;
            int row = i >> 3;
            int c8  = (i & 7) * 8;
            uint32_t doff = row * 144 + c8 * 2;
            CP16(st + AST_KHI + doff, kh + row * NH + c8);
            CP16(st + AST_KLO + doff, kl + row * NH + c8);
        }
        const __nv_bfloat16* vh = g_vthi + (size_t)bb * NH * NT + k0;
        const __nv_bfloat16* vl = g_vtlo + (size_t)bb * NH * NT + k0;
#pragma unroll
        for (int it = 0; it < 4; ++it) {
            int i  = t + it * 128;
            int h  = i >> 3;
            int k8 = (i & 7) * 8;
            uint32_t doff = h * 144 + k8 * 2;
            CP16(st + AST_VHI + doff, vh + (size_t)h * NT + k8);
            CP16(st + AST_VLO + doff, vl + (size_t)h * NT + k8);
        }
    };
    auto load_q = [&](int bb, int qii) {
        const __nv_bfloat16* qh = g_qhi + ((size_t)bb * NT + qii * 128) * NH;
        const __nv_bfloat16* ql = g_qlo + ((size_t)bb * NT + qii * 128) * NH;
#pragma unroll
        for (int it = 0; it < 8; ++it) {
            int i   = t + it * 128;
            int row = i >> 3;
            int c8  = (i & 7) * 8;
            uint32_t doff = row * 144 + c8 * 2;
            *reinterpret_cast<uint4*>(smem + SM_Q_HI + doff) =
                *reinterpret_cast<const uint4*>(qh + row * NH + c8);
            *reinterpret_cast<uint4*>(smem + SM_Q_LO + doff) =
                *reinterpret_cast<const uint4*>(ql + row * NH + c8);
        }
    };

    float o[2][8][4], l[2][2];
    auto zero_acc = [&]() {
#pragma unroll
        for (int mt = 0; mt < 2; ++mt) {
#pragma unroll
            for (int j = 0; j < 8; ++j)
#pragma unroll
                for (int c = 0; c < 4; ++c) o[mt][j][c] = 0.f;
            l[mt][0] = l[mt][1] = 0.f;
        }
    };
    auto flush = [&](int bb, int qii) {
#pragma unroll
        for (int mt = 0; mt < 2; ++mt) {
            float r0 = l[mt][0], r1 = l[mt][1];
            r0 += __shfl_xor_sync(0xffffffffu, r0, 1);
            r0 += __shfl_xor_sync(0xffffffffu, r0, 2);
            r1 += __shfl_xor_sync(0xffffffffu, r1, 1);
            r1 += __shfl_xor_sync(0xffffffffu, r1, 2);
            int rra = bb * NT + qii * 128 + 32 * w + 16 * mt + (lane >> 2);
            if ((lane & 3) == 0) {
                atomicAdd(&g_lacc[rra], r0);
                atomicAdd(&g_lacc[rra + 8], r1);
            }
            float* o0 = g_oacc + (size_t)rra * NH;
            float* o1 = g_oacc + (size_t)(rra + 8) * NH;
#pragma unroll
            for (int j = 0; j < 8; ++j) {
                int h = 8 * j + 2 * (lane & 3);
                atomicAdd(o0 + h,     o[mt][j][0]);
                atomicAdd(o0 + h + 1, o[mt][j][1]);
                atomicAdd(o1 + h,     o[mt][j][2]);
                atomicAdd(o1 + h + 1, o[mt][j][3]);
            }
        }
    };

    // ---- prologue ----
    issue_kv(0, b, kb);
    CP_COMMIT();
    load_q(b, qi);
    __syncthreads();
    zero_acc();

    // Q fragments cached across k-tiles; rebuilt only on q-tile change.
    uint32_t qh[2][4][4], ql[2][4][4];
    bool qfresh = true;

    for (int it = 0; it < cnt; ++it) {
        int nb = b, nqi = qi, nkb = kb + 1;
        bool changed = false;
        if (nkb > 2 * qi + 1) {
            nkb = 0; ++nqi; changed = true;
            if (nqi == 32) { nqi = 0; ++nb; }
        }
        const bool last = (it == cnt - 1);

        CP_WAIT0();
        __syncthreads();
        if (!last) { issue_kv((it + 1) & 1, nb, nkb); CP_COMMIT(); }

        const uint32_t st = sb + (it & 1) * AST_SZ;
        const int k0 = kb * 64;
        const int q0 = qi * 128;
        const bool diag = (kb >= 2 * qi);

        if (qfresh) {
#pragma unroll
            for (int mt = 0; mt < 2; ++mt)
#pragma unroll
                for (int ks = 0; ks < 4; ++ks) {
                    uint32_t a = sb + SM_Q_HI + qpat + mt * (16 * 144) + ks * 32;
                    ldsm_x4(qh[mt][ks], a);
                    ldsm_x4(ql[mt][ks], a + 18432);
                }
            qfresh = false;
        }

        // ---- S = Q K^T : shared K fragments feed both m-tiles ----
        float s[2][8][4];
#pragma unroll
        for (int mt = 0; mt < 2; ++mt)
#pragma unroll
            for (int j = 0; j < 8; ++j)
#pragma unroll
                for (int c = 0; c < 4; ++c) s[mt][j][c] = 0.f;
#pragma unroll
        for (int j2 = 0; j2 < 4; ++j2) {
#pragma unroll
            for (int ks = 0; ks < 4; ++ks) {
                uint32_t kh[4], kl[4];
                uint32_t a = st + kpat + j2 * (16 * 144) + ks * 32;
                ldsm_x4(kh, a + AST_KHI);
                ldsm_x4(kl, a + AST_KLO);
#pragma unroll
                for (int mt = 0; mt < 2; ++mt) {
                    float* sA = s[mt][2 * j2];
                    float* sB = s[mt][2 * j2 + 1];
                    mma_bf16(sA, qh[mt][ks], kh[0], kh[1]);
                    mma_bf16(sA, qh[mt][ks], kl[0], kl[1]);
                    mma_bf16(sA, ql[mt][ks], kh[0], kh[1]);
                    mma_bf16(sB, qh[mt][ks], kh[2], kh[3]);
                    mma_bf16(sB, qh[mt][ks], kl[2], kl[3]);
                    mma_bf16(sB, ql[mt][ks], kh[2], kh[3]);
                }
            }
        }

        // ---- exp2 (+ causal mask on diagonal tiles) ----
#pragma unroll
        for (int mt = 0; mt < 2; ++mt) {
            const int ra = q0 + 32 * w + 16 * mt + (lane >> 2);
            if (diag) {
#pragma unroll
                for (int j = 0; j < 8; ++j) {
                    int col = k0 + 8 * j + 2 * (lane & 3);
                    float e0 = (col     <= ra)     ? ex2f(s[mt][j][0]) : 0.f;
                    float e1 = (col + 1 <= ra)     ? ex2f(s[mt][j][1]) : 0.f;
                    float e2 = (col     <= ra + 8) ? ex2f(s[mt][j][2]) : 0.f;
                    float e3 = (col + 1 <= ra + 8) ? ex2f(s[mt][j][3]) : 0.f;
                    s[mt][j][0] = e0; s[mt][j][1] = e1;
                    s[mt][j][2] = e2; s[mt][j][3] = e3;
                    l[mt][0] += e0 + e1; l[mt][1] += e2 + e3;
                }
            } else {
#pragma unroll
                for (int j = 0; j < 8; ++j) {
                    float e0 = ex2f(s[mt][j][0]);
                    float e1 = ex2f(s[mt][j][1]);
                    float e2 = ex2f(s[mt][j][2]);
                    float e3 = ex2f(s[mt][j][3]);
                    s[mt][j][0] = e0; s[mt][j][1] = e1;
                    s[mt][j][2] = e2; s[mt][j][3] = e3;
                    l[mt][0] += e0 + e1; l[mt][1] += e2 + e3;
                }
            }
        }

        // ---- O += P V : shared V fragments feed both m-tiles ----
#pragma unroll
        for (int kc = 0; kc < 4; ++kc) {
            uint32_t ah[2][4], al[2][4];
#pragma unroll
            for (int mt = 0; mt < 2; ++mt)
#pragma unroll
                for (int half = 0; half < 2; ++half) {
                    const float* sp = s[mt][2 * kc + half];
                    float h0 = __bfloat162float(__float2bfloat16(sp[0]));
                    float h1 = __bfloat162float(__float2bfloat16(sp[1]));
                    float h2 = __bfloat162float(__float2bfloat16(sp[2]));
                    float h3 = __bfloat162float(__float2bfloat16(sp[3]));
                    ah[mt][2 * half + 0] = pack_bf16x2(sp[0], sp[1]);
                    ah[mt][2 * half + 1] = pack_bf16x2(sp[2], sp[3]);
                    al[mt][2 * half + 0] = pack_bf16x2(sp[0] - h0, sp[1] - h1);
                    al[mt][2 * half + 1] = pack_bf16x2(sp[2] - h2, sp[3] - h3);
                }
#pragma unroll
            for (int jp = 0; jp < 4; ++jp) {
                uint32_t vh[4], vl[4];
                uint32_t a = st + AST_VHI + vpat + jp * (16 * 144) + kc * 32;
                ldsm_x4(vh, a);
                ldsm_x4(vl, a + (AST_VLO - AST_VHI));
#pragma unroll
                for (int mt = 0; mt < 2; ++mt) {
                    mma_bf16(o[mt][2 * jp],     ah[mt], vh[0], vh[1]);
                    mma_bf16(o[mt][2 * jp],     al[mt], vh[0], vh[1]);
                    mma_bf16(o[mt][2 * jp],     ah[mt], vl[0], vl[1]);
                    mma_bf16(o[mt][2 * jp + 1], ah[mt], vh[2], vh[3]);
                    mma_bf16(o[mt][2 * jp + 1], al[mt], vh[2], vh[3]);
                    mma_bf16(o[mt][2 * jp + 1], ah[mt], vl[2], vl[3]);
                }
            }
        }

        if (!last && changed) {
            flush(b, qi);
            load_q(nb, nqi);
            zero_acc();
            qfresh = true;
        }
        b = nb; qi = nqi; kb = nkb;
    }
    // final flush: recover indices of the last computed tile
    {
        int pb = b, pqi = qi;
        if (kb == 0) {
            if (pqi == 0) { --pb; pqi = 32; }
            --pqi;
        }
        flush(pb, pqi);
    }
}

// ===========================================================================
// Kernel 3: normalize — out = O / l   (one float4 per thread, full chip)
// ===========================================================================
__global__ void norm_kernel(float* __restrict__ out)
{
    const int i = blockIdx.x * 256 + threadIdx.x;       // 262144 = NROWS*NH/4
    float4 v = reinterpret_cast<const float4*>(g_oacc)[i];
    float linv = 1.f / g_lacc[i >> 4];
    v.x *= linv; v.y *= linv; v.z *= linv; v.w *= linv;
    reinterpret_cast<float4*>(out)[i] = v;
}

// ===========================================================================
extern "C" void kernel_launch(void* const* d_in, const int* in_sizes, int n_in,
                              void* d_out, int out_size)
{
    (void)in_sizes; (void)n_in; (void)out_size;
    const float* x  = (const float*)d_in[0];
    const float* Wq = (const float*)d_in[1];
    const float* Wk = (const float*)d_in[2];
    const float* Wv = (const float*)d_in[3];
    float* out = (float*)d_out;

    cudaFuncSetAttribute(qkv_mma, cudaFuncAttributeMaxDynamicSharedMemorySize, QS_TOTAL);
    cudaFuncSetAttribute(attn_mma, cudaFuncAttributeMaxDynamicSharedMemorySize, SM_ATT_TOTAL);

    init_kernel<<<512, 256>>>(Wq, Wk, Wv);
    qkv_mma<<<128, 256, QS_TOTAL>>>(x);
    attn_mma<<<296, 128, SM_ATT_TOTAL>>>();
    norm_kernel<<<1024, 256>>>(out);
}